// round 1
// baseline (speedup 1.0000x reference)
#include <cuda_runtime.h>
#include <cuda_bf16.h>

// ---------------------------------------------------------------------------
// GuidedAttentionL1Loss
//   out[0] = loss = nll + (ALPHA/2)*sum|params| + (BETA/2)*mean_b(seg(diff^2)/len_b)
//   out[1] = nll
// Strategy: one CTA per segment; segment y cached in SMEM so attn_weights is
// read from DRAM exactly once. r_hat cached in SMEM (exp evaluated once).
// lengths prefix-scanned on device (seg_ids unused). int32/int64 auto-detect.
// ---------------------------------------------------------------------------

#define MAX_B 4096
#define MAX_LEN 3072
#define ALPHA_HALF 5.0e-4
#define BETA_HALF 0.05

__device__ double g_psum;
__device__ double g_nll;
__device__ double g_attn;
__device__ int g_starts[MAX_B];

__device__ __forceinline__ bool detect_i64(const void* lengths) {
    // lengths[0] >= 1 always; if stored as little-endian int64 the second
    // 32-bit word is the high word of lengths[0] == 0. If int32, it is
    // lengths[1] >= 1 != 0.
    return ((const int*)lengths)[1] == 0;
}

__device__ __forceinline__ long long load_int(const void* p, int i, bool is64) {
    return is64 ? ((const long long*)p)[i] : (long long)((const int*)p)[i];
}

// Block-wide sum with broadcast. `red` must hold >= 32 floats.
__device__ __forceinline__ float block_sum(float v, float* red) {
    int lane = threadIdx.x & 31;
    int w = threadIdx.x >> 5;
#pragma unroll
    for (int o = 16; o > 0; o >>= 1) v += __shfl_down_sync(0xffffffffu, v, o);
    __syncthreads();               // protect red from previous use
    if (lane == 0) red[w] = v;
    __syncthreads();
    if (w == 0) {
        int nw = (blockDim.x + 31) >> 5;
        v = (lane < nw) ? red[lane] : 0.0f;
#pragma unroll
        for (int o = 4; o > 0; o >>= 1) v += __shfl_down_sync(0xffffffffu, v, o);
        if (lane == 0) red[0] = v;
    }
    __syncthreads();
    return red[0];
}

// ---------------------------------------------------------------------------
// Kernel 1: zero accumulators + prefix scan of lengths -> g_starts.
// One block, 1024 threads, 4 items/thread (B <= 4096).
// ---------------------------------------------------------------------------
__global__ __launch_bounds__(1024) void scan_kernel(const void* lengths, int B) {
    __shared__ int part[1024];
    int t = threadIdx.x;
    if (t == 0) { g_psum = 0.0; g_nll = 0.0; g_attn = 0.0; }
    bool is64 = detect_i64(lengths);

    int l[4];
    int base = t * 4;
#pragma unroll
    for (int j = 0; j < 4; j++)
        l[j] = (base + j < B) ? (int)load_int(lengths, base + j, is64) : 0;
    int tot = l[0] + l[1] + l[2] + l[3];
    part[t] = tot;
    __syncthreads();
    // Hillis-Steele inclusive scan over 1024 partials
#pragma unroll
    for (int off = 1; off < 1024; off <<= 1) {
        int add = (t >= off) ? part[t - off] : 0;
        __syncthreads();
        part[t] += add;
        __syncthreads();
    }
    int excl = part[t] - tot;  // exclusive prefix for this thread's chunk
    int run = excl;
#pragma unroll
    for (int j = 0; j < 4; j++) {
        if (base + j < B) g_starts[base + j] = run;
        run += l[j];
    }
}

// ---------------------------------------------------------------------------
// Kernel 2: L1 penalty sum over params + NLL over logits/labels.
// ---------------------------------------------------------------------------
__global__ __launch_bounds__(256) void misc_kernel(
    const float* __restrict__ logits, const float* __restrict__ params,
    const void* __restrict__ labels, const void* __restrict__ lengths,
    int P, int B)
{
    __shared__ float red[32];
    int gid = blockIdx.x * blockDim.x + threadIdx.x;
    int stride = gridDim.x * blockDim.x;

    // L1 over params (P divisible by 4 -> float4)
    float a = 0.0f;
    const float4* p4 = (const float4*)params;
    int n4 = P >> 2;
    for (int i = gid; i < n4; i += stride) {
        float4 v = p4[i];
        a += fabsf(v.x) + fabsf(v.y) + fabsf(v.z) + fabsf(v.w);
    }
    float A = block_sum(a, red);
    if (threadIdx.x == 0 && A != 0.0f) atomicAdd(&g_psum, (double)A);

    // NLL over B rows of 2-class logits
    bool is64 = detect_i64(lengths);
    float nl = 0.0f;
    for (int b = gid; b < B; b += stride) {
        float l0 = logits[2 * b];
        float l1 = logits[2 * b + 1];
        int lab = (int)load_int(labels, b, is64);
        float m = fmaxf(l0, l1);
        float lse = m + logf(expf(l0 - m) + expf(l1 - m));
        float lp = (lab ? l1 : l0) - lse;
        nl -= lp;
    }
    float NL = block_sum(nl, red);
    if (threadIdx.x == 0 && NL != 0.0f) atomicAdd(&g_nll, (double)NL);
}

// ---------------------------------------------------------------------------
// Kernel 3: per-segment attention penalty. One block per segment.
// ---------------------------------------------------------------------------
__global__ __launch_bounds__(256) void seg_kernel(
    const float* __restrict__ attn,
    const void* __restrict__ labels, const void* __restrict__ lengths)
{
    __shared__ float sy[MAX_LEN];
    __shared__ float srh[MAX_LEN];
    __shared__ float red[32];

    int b = blockIdx.x;
    bool is64 = detect_i64(lengths);
    int len = (int)load_int(lengths, b, is64);
    int lab = (int)load_int(labels, b, is64);
    int start = g_starts[b];
    int t = threadIdx.x;

    float lenf = (float)len;
    float inv_len = 1.0f / lenf;

    // Pass 1: load y into SMEM, accumulate sum_y and sum_xy
    float s_y = 0.0f, s_xy = 0.0f;
    for (int i = t; i < len; i += 256) {
        float yv = __ldg(&attn[start + i]);
        sy[i] = yv;
        float x = (float)(i + 1) * inv_len;
        s_y += yv;
        s_xy += x * yv;
    }
    float SY = block_sum(s_y, red);
    float SXY = block_sum(s_xy, red);
    float mean = SXY / SY;

    float stdv = (lab == 1 ? 1.0f : 1000.0f) * inv_len;
    float inv_std = 1.0f / stdv;
    float inv_norm = inv_std * 0.3989422804014327f;  // 1/sqrt(2*pi)

    // Pass 2: r_hat into SMEM, accumulate its sum. exp skipped when negligible.
    float s_rh = 0.0f;
    for (int i = t; i < len; i += 256) {
        float x = (float)(i + 1) * inv_len;
        float z = (x - mean) * inv_std;
        float z2 = z * z;
        float rh = 0.0f;
        if (z2 < 80.0f) rh = __expf(-0.5f * z2) * inv_norm;
        srh[i] = rh;
        s_rh += rh;
    }
    float SRH = block_sum(s_rh, red);
    float rscale = 1.0f / (SRH + 1e-6f);

    // Pass 3: sum of (y - r)^2, all from SMEM
    float d2 = 0.0f;
    for (int i = t; i < len; i += 256) {
        float diff = sy[i] - srh[i] * rscale;
        d2 += diff * diff;
    }
    float D2 = block_sum(d2, red);
    if (t == 0) atomicAdd(&g_attn, (double)(D2 * inv_len));
}

// ---------------------------------------------------------------------------
// Kernel 4: finalize
// ---------------------------------------------------------------------------
__global__ void fin_kernel(float* out, int out_size, double invB) {
    double nll = g_nll * invB;
    double loss = nll + ALPHA_HALF * g_psum + BETA_HALF * (g_attn * invB);
    out[0] = (float)loss;
    if (out_size > 1) out[1] = (float)nll;
}

extern "C" void kernel_launch(void* const* d_in, const int* in_sizes, int n_in,
                              void* d_out, int out_size) {
    const float* logits = (const float*)d_in[0];   // [B,2] f32
    const float* params = (const float*)d_in[1];   // [P]   f32
    const float* attn   = (const float*)d_in[2];   // [T]   f32
    const void*  labels = d_in[3];                 // [B]   int32/int64
    const void*  lengths= d_in[4];                 // [B]   int32/int64
    // d_in[5] = seg_ids: unused (replaced by on-device prefix scan)

    int P = in_sizes[1];
    int B = in_sizes[3];

    scan_kernel<<<1, 1024>>>(lengths, B);
    misc_kernel<<<296, 256>>>(logits, params, labels, lengths, P, B);
    seg_kernel<<<B, 256>>>(attn, labels, lengths);
    fin_kernel<<<1, 1>>>((float*)d_out, out_size, 1.0 / (double)B);
}

// round 2
// speedup vs baseline: 1.0929x; 1.0929x over previous
#include <cuda_runtime.h>
#include <cuda_bf16.h>

// ---------------------------------------------------------------------------
// GuidedAttentionL1Loss — 2-launch version
//   launch 1: 1-block prefix scan of lengths -> g_starts
//   launch 2: fused kernel
//       blocks [0, NMISC)          : params L1 + NLL
//       blocks [NMISC, NMISC+B)    : per-segment attention penalty
//       last block to finish       : finalize loss, write out, reset globals
// Pass-3 elimination: sum(y-r)^2 = Sy2 - 2*rs*Syrh + rs^2*Srh2
// ---------------------------------------------------------------------------

#define MAX_B 4096
#define MAX_LEN 3072
#define NMISC 148
#define ALPHA_HALF 5.0e-4
#define BETA_HALF 0.05

__device__ double g_psum = 0.0;
__device__ double g_nll  = 0.0;
__device__ double g_attn = 0.0;
__device__ int    g_done = 0;
__device__ int    g_starts[MAX_B];

__device__ __forceinline__ bool detect_i64(const void* lengths) {
    // lengths[0] >= 1 always; int64 little-endian -> second 32-bit word == 0.
    return ((const int*)lengths)[1] == 0;
}

__device__ __forceinline__ long long load_int(const void* p, int i, bool is64) {
    return is64 ? ((const long long*)p)[i] : (long long)((const int*)p)[i];
}

// Reduce three floats block-wide simultaneously; results broadcast.
__device__ __forceinline__ void block_sum3(float& a, float& b, float& c,
                                           float (*red)[32]) {
    int lane = threadIdx.x & 31;
    int w = threadIdx.x >> 5;
#pragma unroll
    for (int o = 16; o > 0; o >>= 1) {
        a += __shfl_down_sync(0xffffffffu, a, o);
        b += __shfl_down_sync(0xffffffffu, b, o);
        c += __shfl_down_sync(0xffffffffu, c, o);
    }
    __syncthreads();
    if (lane == 0) { red[0][w] = a; red[1][w] = b; red[2][w] = c; }
    __syncthreads();
    if (w == 0) {
        int nw = (blockDim.x + 31) >> 5;
        a = (lane < nw) ? red[0][lane] : 0.0f;
        b = (lane < nw) ? red[1][lane] : 0.0f;
        c = (lane < nw) ? red[2][lane] : 0.0f;
#pragma unroll
        for (int o = 4; o > 0; o >>= 1) {
            a += __shfl_down_sync(0xffffffffu, a, o);
            b += __shfl_down_sync(0xffffffffu, b, o);
            c += __shfl_down_sync(0xffffffffu, c, o);
        }
        if (lane == 0) { red[0][0] = a; red[1][0] = b; red[2][0] = c; }
    }
    __syncthreads();
    a = red[0][0]; b = red[1][0]; c = red[2][0];
}

// ---------------------------------------------------------------------------
// Launch 1: prefix scan of lengths -> g_starts (exclusive).
// ---------------------------------------------------------------------------
__global__ __launch_bounds__(1024) void scan_kernel(const void* lengths, int B) {
    __shared__ int part[1024];
    int t = threadIdx.x;
    bool is64 = detect_i64(lengths);

    int l[4];
    int base = t * 4;
#pragma unroll
    for (int j = 0; j < 4; j++)
        l[j] = (base + j < B) ? (int)load_int(lengths, base + j, is64) : 0;
    int tot = l[0] + l[1] + l[2] + l[3];
    part[t] = tot;
    __syncthreads();
#pragma unroll
    for (int off = 1; off < 1024; off <<= 1) {
        int add = (t >= off) ? part[t - off] : 0;
        __syncthreads();
        part[t] += add;
        __syncthreads();
    }
    int run = part[t] - tot;
#pragma unroll
    for (int j = 0; j < 4; j++) {
        if (base + j < B) g_starts[base + j] = run;
        run += l[j];
    }
}

// ---------------------------------------------------------------------------
// Launch 2: fused misc + segments + finalize.
// ---------------------------------------------------------------------------
__global__ __launch_bounds__(256) void fused_kernel(
    const float* __restrict__ logits, const float* __restrict__ params,
    const float* __restrict__ attn,
    const void* __restrict__ labels, const void* __restrict__ lengths,
    int P, int B, float* __restrict__ out, int out_size)
{
    __shared__ float sy[MAX_LEN];
    __shared__ float red[3][32];

    int t = threadIdx.x;
    bool is64 = detect_i64(lengths);

    if (blockIdx.x < NMISC) {
        // ----- misc: L1 over params + NLL over logits -----
        int gid = blockIdx.x * 256 + t;
        int stride = NMISC * 256;

        float a = 0.0f;
        const float4* p4 = (const float4*)params;
        int n4 = P >> 2;
        for (int i = gid; i < n4; i += stride) {
            float4 v = p4[i];
            a += fabsf(v.x) + fabsf(v.y) + fabsf(v.z) + fabsf(v.w);
        }

        float nl = 0.0f;
        for (int b = gid; b < B; b += stride) {
            float l0 = logits[2 * b];
            float l1 = logits[2 * b + 1];
            int lab = (int)load_int(labels, b, is64);
            float m = fmaxf(l0, l1);
            float lse = m + logf(expf(l0 - m) + expf(l1 - m));
            nl -= (lab ? l1 : l0) - lse;
        }
        float dummy = 0.0f;
        block_sum3(a, nl, dummy, red);
        if (t == 0) {
            if (a != 0.0f)  atomicAdd(&g_psum, (double)a);
            if (nl != 0.0f) atomicAdd(&g_nll, (double)nl);
        }
    } else {
        // ----- one segment per block -----
        int b = blockIdx.x - NMISC;
        int len = (int)load_int(lengths, b, is64);
        int lab = (int)load_int(labels, b, is64);
        int start = g_starts[b];

        float inv_len = 1.0f / (float)len;

        // Pass 1: y -> SMEM; accumulate Sy, Sxy, Sy2
        float s_y = 0.0f, s_xy = 0.0f, s_y2 = 0.0f;
#pragma unroll 4
        for (int i = t; i < len; i += 256) {
            float yv = __ldg(&attn[start + i]);
            sy[i] = yv;
            float x = (float)(i + 1) * inv_len;
            s_y += yv;
            s_xy = fmaf(x, yv, s_xy);
            s_y2 = fmaf(yv, yv, s_y2);
        }
        block_sum3(s_y, s_xy, s_y2, red);
        float mean = s_xy / s_y;

        float stdv = (lab == 1 ? 1.0f : 1000.0f) * inv_len;
        float inv_std = 1.0f / stdv;
        float inv_norm = inv_std * 0.3989422804014327f;  // 1/sqrt(2*pi)

        // Pass 2: accumulate Srh, Syrh, Srh2 (rh from SMEM-cached y)
        float s_rh = 0.0f, s_yrh = 0.0f, s_rh2 = 0.0f;
#pragma unroll 4
        for (int i = t; i < len; i += 256) {
            float x = (float)(i + 1) * inv_len;
            float z = (x - mean) * inv_std;
            float z2 = z * z;
            if (z2 < 80.0f) {
                float rh = __expf(-0.5f * z2) * inv_norm;
                s_rh += rh;
                s_yrh = fmaf(sy[i], rh, s_yrh);
                s_rh2 = fmaf(rh, rh, s_rh2);
            }
        }
        block_sum3(s_rh, s_yrh, s_rh2, red);

        if (t == 0) {
            float rs = 1.0f / (s_rh + 1e-6f);
            float D2 = s_y2 - 2.0f * rs * s_yrh + rs * rs * s_rh2;
            atomicAdd(&g_attn, (double)(D2 * inv_len));
        }
    }

    // ----- completion counter; last block finalizes and resets -----
    __threadfence();
    __syncthreads();
    if (t == 0) {
        int prev = atomicAdd(&g_done, 1);
        if (prev == (int)gridDim.x - 1) {
            double invB = 1.0 / (double)B;
            double nll = g_nll * invB;
            double loss = nll + ALPHA_HALF * g_psum + BETA_HALF * (g_attn * invB);
            out[0] = (float)loss;
            if (out_size > 1) out[1] = (float)nll;
            // reset for next graph replay
            g_psum = 0.0; g_nll = 0.0; g_attn = 0.0;
            __threadfence();
            g_done = 0;
        }
    }
}

extern "C" void kernel_launch(void* const* d_in, const int* in_sizes, int n_in,
                              void* d_out, int out_size) {
    const float* logits  = (const float*)d_in[0];   // [B,2] f32
    const float* params  = (const float*)d_in[1];   // [P]   f32
    const float* attn    = (const float*)d_in[2];   // [T]   f32
    const void*  labels  = d_in[3];                 // [B]   int32/int64
    const void*  lengths = d_in[4];                 // [B]   int32/int64
    // d_in[5] = seg_ids: unused

    int P = in_sizes[1];
    int B = in_sizes[3];

    scan_kernel<<<1, 1024>>>(lengths, B);
    fused_kernel<<<NMISC + B, 256>>>(logits, params, attn, labels, lengths,
                                     P, B, (float*)d_out, out_size);
}

// round 3
// speedup vs baseline: 1.1402x; 1.0432x over previous
#include <cuda_runtime.h>
#include <cuda_bf16.h>

// ---------------------------------------------------------------------------
// GuidedAttentionL1Loss — 2 launches
//  launch 1: warp-shuffle prefix scan of lengths -> g_starts
//  launch 2: fused misc (L1+NLL) + per-segment penalty + last-block finalize
// Key: y register-cached (no smem traffic); incremental x; label==1 segments
// use analytic Gaussian support window (<=19 elems); 1/sqrt(2pi) folded out.
// ---------------------------------------------------------------------------

#define MAX_B 4096
#define MAXIT 12           // MAX_LEN 3072 / 256 threads
#define NMISC 148
#define ALPHA_HALF 5.0e-4
#define BETA_HALF 0.05

__device__ double g_psum = 0.0;
__device__ double g_nll  = 0.0;
__device__ double g_attn = 0.0;
__device__ int    g_done = 0;
__device__ int    g_starts[MAX_B];

__device__ __forceinline__ bool detect_i64(const void* lengths) {
    // lengths[0] >= 1 always; int64 LE -> high word of elem 0 is 0.
    return ((const int*)lengths)[1] == 0;
}
__device__ __forceinline__ int load_int(const void* p, int i, bool is64) {
    return is64 ? (int)((const long long*)p)[i] : ((const int*)p)[i];
}
__device__ __forceinline__ float ex2(float a) {
    float r;
    asm("ex2.approx.ftz.f32 %0, %1;" : "=f"(r) : "f"(a));
    return r;
}

// Reduce three floats block-wide; results broadcast to all threads.
__device__ __forceinline__ void block_sum3(float& a, float& b, float& c,
                                           float (*red)[32]) {
    int lane = threadIdx.x & 31;
    int w = threadIdx.x >> 5;
#pragma unroll
    for (int o = 16; o > 0; o >>= 1) {
        a += __shfl_down_sync(0xffffffffu, a, o);
        b += __shfl_down_sync(0xffffffffu, b, o);
        c += __shfl_down_sync(0xffffffffu, c, o);
    }
    __syncthreads();
    if (lane == 0) { red[0][w] = a; red[1][w] = b; red[2][w] = c; }
    __syncthreads();
    if (w == 0) {
        int nw = blockDim.x >> 5;
        a = (lane < nw) ? red[0][lane] : 0.0f;
        b = (lane < nw) ? red[1][lane] : 0.0f;
        c = (lane < nw) ? red[2][lane] : 0.0f;
#pragma unroll
        for (int o = 4; o > 0; o >>= 1) {
            a += __shfl_down_sync(0xffffffffu, a, o);
            b += __shfl_down_sync(0xffffffffu, b, o);
            c += __shfl_down_sync(0xffffffffu, c, o);
        }
        if (lane == 0) { red[0][0] = a; red[1][0] = b; red[2][0] = c; }
    }
    __syncthreads();
    a = red[0][0]; b = red[1][0]; c = red[2][0];
}

// ---------------------------------------------------------------------------
// Launch 1: exclusive prefix scan of lengths (B <= 4096), shuffle-based.
// ---------------------------------------------------------------------------
__global__ __launch_bounds__(1024) void scan_kernel(const void* lengths, int B) {
    __shared__ int wsum[32];
    int t = threadIdx.x;
    int lane = t & 31, w = t >> 5;
    bool is64 = detect_i64(lengths);

    int l[4];
    int base = t * 4;
#pragma unroll
    for (int j = 0; j < 4; j++)
        l[j] = (base + j < B) ? load_int(lengths, base + j, is64) : 0;
    int tot = l[0] + l[1] + l[2] + l[3];

    // inclusive warp scan of tot
    int inc = tot;
#pragma unroll
    for (int o = 1; o < 32; o <<= 1) {
        int v = __shfl_up_sync(0xffffffffu, inc, o);
        if (lane >= o) inc += v;
    }
    if (lane == 31) wsum[w] = inc;
    __syncthreads();
    if (w == 0) {
        int v = wsum[lane];
#pragma unroll
        for (int o = 1; o < 32; o <<= 1) {
            int u = __shfl_up_sync(0xffffffffu, v, o);
            if (lane >= o) v += u;
        }
        wsum[lane] = v;
    }
    __syncthreads();
    int warp_base = (w > 0) ? wsum[w - 1] : 0;
    int run = warp_base + inc - tot;   // exclusive prefix for this thread
#pragma unroll
    for (int j = 0; j < 4; j++) {
        if (base + j < B) g_starts[base + j] = run;
        run += l[j];
    }
}

// ---------------------------------------------------------------------------
// Launch 2: fused.
// ---------------------------------------------------------------------------
__global__ __launch_bounds__(256) void fused_kernel(
    const float* __restrict__ logits, const float* __restrict__ params,
    const float* __restrict__ attn,
    const void* __restrict__ labels, const void* __restrict__ lengths,
    int P, int B, float* __restrict__ out, int out_size)
{
    __shared__ float red[3][32];
    int t = threadIdx.x;
    bool is64 = detect_i64(lengths);

    if (blockIdx.x < NMISC) {
        // ----- misc: L1 over params + NLL over logits -----
        int gid = blockIdx.x * 256 + t;
        int stride = NMISC * 256;

        float a = 0.0f;
        const float4* p4 = (const float4*)params;
        int n4 = P >> 2;
        for (int i = gid; i < n4; i += stride) {
            float4 v = p4[i];
            a += fabsf(v.x) + fabsf(v.y) + fabsf(v.z) + fabsf(v.w);
        }
        float nl = 0.0f;
        for (int b = gid; b < B; b += stride) {
            float l0 = logits[2 * b];
            float l1 = logits[2 * b + 1];
            int lab = load_int(labels, b, is64);
            float m = fmaxf(l0, l1);
            float lse = m + logf(expf(l0 - m) + expf(l1 - m));
            nl -= (lab ? l1 : l0) - lse;
        }
        float dummy = 0.0f;
        block_sum3(a, nl, dummy, red);
        if (t == 0) {
            if (a != 0.0f)  atomicAdd(&g_psum, (double)a);
            if (nl != 0.0f) atomicAdd(&g_nll, (double)nl);
        }
    } else {
        // ----- one segment per block -----
        int b = blockIdx.x - NMISC;
        int len = load_int(lengths, b, is64);
        int lab = load_int(labels, b, is64);
        int start = g_starts[b];

        float inv_len = 1.0f / (float)len;
        float dx = 256.0f * inv_len;
        // iterations valid for this thread
        int nit = (len - t + 255) >> 8;   // = #i in {t, t+256, ...} < len

        // Pass 1: y -> registers; Sy, Sxy, Sy2. x incremental.
        float ry[MAXIT];
        float s_y = 0.0f, s_xy = 0.0f, s_y2 = 0.0f;
        float x = (float)(t + 1) * inv_len;
        const float* ap = attn + start + t;
#pragma unroll
        for (int j = 0; j < MAXIT; j++) {
            if (j < nit) {
                float yv = __ldg(ap + (j << 8));
                ry[j] = yv;
                s_y += yv;
                s_xy = fmaf(x, yv, s_xy);
                s_y2 = fmaf(yv, yv, s_y2);
            }
            x += dx;
        }
        block_sum3(s_y, s_xy, s_y2, red);
        float mean = s_xy / s_y;

        float inv_std = (lab == 1) ? (float)len : (float)len * 1e-3f;
        // eps' = 1e-6 / inv_norm = 1e-6*sqrt(2pi)/inv_std
        float epsp = 2.5066283e-6f / inv_std;

        float s_e = 0.0f, s_ye = 0.0f, s_e2 = 0.0f;
        if (lab == 1) {
            // Gaussian support: z = (i+1 - mean*len), spacing 1; z^2<81 -> <=19 elems
            float c = mean * (float)len;
            int i_lo = (int)ceilf(c - 9.0f) - 1;
            if (i_lo < 0) i_lo = 0;
            int i_hi = (int)floorf(c + 9.0f) - 1;
            if (i_hi > len - 1) i_hi = len - 1;
            if (t <= i_hi - i_lo) {
                int i = i_lo + t;
                float yv = __ldg(&attn[start + i]);
                float d = (float)(i + 1) * inv_len - mean;
                float z = d * inv_std;
                float e = ex2(-0.72134752f * z * z);  // exp(-z^2/2)
                s_e = e;
                s_ye = yv * e;
                s_e2 = e * e;
            }
        } else {
            // z^2 <= ~9.44 always: no guard, exp everywhere (y from registers)
            x = (float)(t + 1) * inv_len;
#pragma unroll
            for (int j = 0; j < MAXIT; j++) {
                if (j < nit) {
                    float d = x - mean;
                    float z = d * inv_std;
                    float e = ex2(-0.72134752f * z * z);
                    s_e += e;
                    s_ye = fmaf(ry[j], e, s_ye);
                    s_e2 = fmaf(e, e, s_e2);
                }
                x += dx;
            }
        }
        block_sum3(s_e, s_ye, s_e2, red);

        if (t == 0) {
            float rs = 1.0f / (s_e + epsp);
            float D2 = s_y2 - 2.0f * rs * s_ye + rs * rs * s_e2;
            atomicAdd(&g_attn, (double)(D2 * inv_len));
        }
    }

    // ----- last block to finish finalizes + resets globals -----
    __threadfence();
    __syncthreads();
    if (t == 0) {
        int prev = atomicAdd(&g_done, 1);
        if (prev == (int)gridDim.x - 1) {
            double invB = 1.0 / (double)B;
            double nll = g_nll * invB;
            double loss = nll + ALPHA_HALF * g_psum + BETA_HALF * (g_attn * invB);
            out[0] = (float)loss;
            if (out_size > 1) out[1] = (float)nll;
            g_psum = 0.0; g_nll = 0.0; g_attn = 0.0;
            __threadfence();
            g_done = 0;
        }
    }
}

extern "C" void kernel_launch(void* const* d_in, const int* in_sizes, int n_in,
                              void* d_out, int out_size) {
    const float* logits  = (const float*)d_in[0];
    const float* params  = (const float*)d_in[1];
    const float* attn    = (const float*)d_in[2];
    const void*  labels  = d_in[3];
    const void*  lengths = d_in[4];
    // d_in[5] = seg_ids: unused

    int P = in_sizes[1];
    int B = in_sizes[3];

    scan_kernel<<<1, 1024>>>(lengths, B);
    fused_kernel<<<NMISC + B, 256>>>(logits, params, attn, labels, lengths,
                                     P, B, (float*)d_out, out_size);
}